// round 10
// baseline (speedup 1.0000x reference)
#include <cuda_runtime.h>
#include <cuda_fp16.h>
#include <cstdint>

// Shapes fixed by dataset: q/k (4,16,4096,64) f32, cos/sin (4,4096,64) f32, vs (32,64) f32
#define DD 64
#define SSS 4096
#define NROWS_Q (4*16*4096)    // 262144
#define NROWS_T (2*NROWS_Q)    // 524288
#define NREFL 32

// mma-ready packed fp16 B fragments, uint2 = {b0, b1}
// GEMM1: B1[k=j][n=i] = Q[i][j]   (Y = X * Q^T)
// GEMM2: B2[k=i][n=j] = Q[i][j]   (O = Z * Q)
__device__ uint2 g_B1[1024];
__device__ uint2 g_B2[1024];

// ---------------- Kernel A: build Q, barrier-free column-owner scan ----------------
__global__ void build_q_kernel(const float* __restrict__ vs) {
    __shared__ __align__(16) float vsh[NREFL*DD];
    __shared__ float coefs[NREFL];
    __shared__ float Qs[DD*DD];
    const int tid  = threadIdx.x;       // 256
    const int lane = tid & 31;
    const int warp = tid >> 5;

    for (int i = tid; i < NREFL*DD/4; i += 256)
        ((float4*)vsh)[i] = ((const float4*)vs)[i];
    __syncthreads();
    if (tid < NREFL) {
        float s = 0.0f;
        const float4* v4 = (const float4*)&vsh[tid*DD];
        #pragma unroll
        for (int c = 0; c < 16; ++c) {
            float4 v = v4[c];
            s += v.x*v.x + v.y*v.y + v.z*v.z + v.w*v.w;
        }
        coefs[tid] = 2.0f / (s + 1e-8f);
    }
    __syncthreads();

    if (warp < 4) {
        const int col = (warp << 4) | (lane & 15);
        const int seg = lane >> 4;
        float qc[32];
        #pragma unroll
        for (int i = 0; i < 32; ++i) qc[i] = (seg*32 + i == col) ? 1.0f : 0.0f;

        for (int r = 0; r < NREFL; ++r) {
            const float4* v4 = (const float4*)&vsh[r*DD + seg*32];
            float4 vv[8];
            #pragma unroll
            for (int i = 0; i < 8; ++i) vv[i] = v4[i];
            float w0 = 0.f, w1 = 0.f, w2 = 0.f, w3 = 0.f;
            #pragma unroll
            for (int i = 0; i < 8; ++i) {
                w0 += vv[i].x * qc[4*i];
                w1 += vv[i].y * qc[4*i+1];
                w2 += vv[i].z * qc[4*i+2];
                w3 += vv[i].w * qc[4*i+3];
            }
            float w = (w0 + w1) + (w2 + w3);
            w += __shfl_xor_sync(0xffffffffu, w, 16);
            float cw = coefs[r] * w;
            #pragma unroll
            for (int i = 0; i < 8; ++i) {
                qc[4*i]   -= vv[i].x * cw;
                qc[4*i+1] -= vv[i].y * cw;
                qc[4*i+2] -= vv[i].z * cw;
                qc[4*i+3] -= vv[i].w * cw;
            }
        }
        #pragma unroll
        for (int i = 0; i < 32; ++i) Qs[(seg*32 + i)*DD + col] = qc[i];
    }
    __syncthreads();

    for (int slot = tid; slot < 1024; slot += 256) {
        int l = slot & 31, frag = slot >> 5;
        int kt = frag >> 3, nt = frag & 7;
        int g = l >> 2, t4 = l & 3;
        int n  = 8*nt + g;
        int k0 = 16*kt + 2*t4;
        {
            __half2 h0 = __floats2half2_rn(Qs[n*DD + k0],     Qs[n*DD + k0 + 1]);
            __half2 h1 = __floats2half2_rn(Qs[n*DD + k0 + 8], Qs[n*DD + k0 + 9]);
            g_B1[slot] = make_uint2(*(uint32_t*)&h0, *(uint32_t*)&h1);
        }
        {
            __half2 h0 = __floats2half2_rn(Qs[k0*DD + n],     Qs[(k0+1)*DD + n]);
            __half2 h1 = __floats2half2_rn(Qs[(k0+8)*DD + n], Qs[(k0+9)*DD + n]);
            g_B2[slot] = make_uint2(*(uint32_t*)&h0, *(uint32_t*)&h1);
        }
    }
}

// ---------------- helpers ----------------
__device__ __forceinline__ void split_f16x2(float a, float b, uint32_t& hi, uint32_t& lo) {
    __half2 h = __floats2half2_rn(a, b);
    float2 hf = __half22float2(h);
    __half2 l = __floats2half2_rn(a - hf.x, b - hf.y);
    hi = *(uint32_t*)&h;
    lo = *(uint32_t*)&l;
}

#define MMA_F16(c, a0, a1, a2, a3, b0, b1)                                         \
    asm volatile("mma.sync.aligned.m16n8k16.row.col.f32.f16.f16.f32 "              \
                 "{%0,%1,%2,%3}, {%4,%5,%6,%7}, {%8,%9}, {%0,%1,%2,%3};"           \
                 : "+f"(c[0]), "+f"(c[1]), "+f"(c[2]), "+f"(c[3])                   \
                 : "r"(a0), "r"(a1), "r"(a2), "r"(a3), "r"(b0), "r"(b1))

// ---------------- Kernel B ----------------
// Block = 128 threads (4 warps), ONE (tensor, b, s-chunk of 8) x 16 heads = 128 rows.
// Each warp: TWO 16-row M-tiles. A fragments built per-kt inside the GEMM loops;
// Z parked in smem (aliasing xs) between the GEMMs -> peak regs ~120 -> 4 blocks/SM.
#define XS_STRIDE 68
__global__ void __launch_bounds__(128, 4) rnrope_mma_kernel(
    const float* __restrict__ qin, const float* __restrict__ kin,
    const float* __restrict__ cosp, const float* __restrict__ sinp,
    float* __restrict__ out)
{
    __shared__ __align__(16) float xs[128 * XS_STRIDE];   // x tile / Z park / out tile
    __shared__ __align__(16) float cs[8 * XS_STRIDE];
    __shared__ __align__(16) float ss[8 * XS_STRIDE];

    const int tid  = threadIdx.x;
    const int warp = tid >> 5;
    const int lane = tid & 31;
    const int g    = lane >> 2;
    const int t4   = lane & 3;

    const int bid    = blockIdx.x;          // 4096 blocks
    const int tensor = bid >> 11;           // 0 = q, 1 = k
    const int b      = (bid >> 9) & 3;
    const int s0     = (bid & 511) << 3;
    const float* src = tensor ? kin : qin;

    // ---- stage cos/sin (8 rows x 64) ----
    {
        int r  = tid >> 4;
        int c4 = (tid & 15) << 2;
        size_t gofs = ((size_t)(b * SSS + s0 + r)) * DD + c4;
        *(float4*)&cs[r * XS_STRIDE + c4] = *(const float4*)(cosp + gofs);
        *(float4*)&ss[r * XS_STRIDE + c4] = *(const float4*)(sinp + gofs);
    }
    // ---- stage x (128 rows x 64), coalesced per 8-row head chunk ----
    #pragma unroll
    for (int it = 0; it < 16; ++it) {
        int lin = it * 128 + tid;
        int rl  = lin >> 4;
        int c4  = (lin & 15) << 2;
        int h   = rl >> 3, ds = rl & 7;
        size_t gofs = (((size_t)(b * 16 + h)) * SSS + s0 + ds) * DD + c4;
        *(float4*)&xs[rl * XS_STRIDE + c4] = *(const float4*)(src + gofs);
    }
    __syncthreads();

    const int tb = warp * 32;
    const float* x0a = &xs[(tb + g) * XS_STRIDE];        // tile0 row g
    const float* x0b = x0a + 8 * XS_STRIDE;              // tile0 row g+8
    const float* x1a = &xs[(tb + 16 + g) * XS_STRIDE];   // tile1
    const float* x1b = x1a + 8 * XS_STRIDE;

    // ---- GEMM1: Y = X * Q^T (2-term fp16), A built per-kt ----
    float C0[8][4], C1[8][4];
    #pragma unroll
    for (int nt = 0; nt < 8; ++nt)
        #pragma unroll
        for (int e = 0; e < 4; ++e) { C0[nt][e] = 0.0f; C1[nt][e] = 0.0f; }

    #pragma unroll
    for (int kt = 0; kt < 4; ++kt) {
        uint2 bb[8];
        #pragma unroll
        for (int nt = 0; nt < 8; ++nt) bb[nt] = g_B1[(kt*8 + nt)*32 + lane];

        const int c0 = kt * 16 + 2 * t4;
        uint32_t ah0[4], al0[4], ah1[4], al1[4];
        {
            float2 p00 = *(const float2*)(x0a + c0);
            float2 p01 = *(const float2*)(x0a + c0 + 8);
            float2 p10 = *(const float2*)(x0b + c0);
            float2 p11 = *(const float2*)(x0b + c0 + 8);
            split_f16x2(p00.x, p00.y, ah0[0], al0[0]);
            split_f16x2(p10.x, p10.y, ah0[1], al0[1]);
            split_f16x2(p01.x, p01.y, ah0[2], al0[2]);
            split_f16x2(p11.x, p11.y, ah0[3], al0[3]);
        }
        {
            float2 p00 = *(const float2*)(x1a + c0);
            float2 p01 = *(const float2*)(x1a + c0 + 8);
            float2 p10 = *(const float2*)(x1b + c0);
            float2 p11 = *(const float2*)(x1b + c0 + 8);
            split_f16x2(p00.x, p00.y, ah1[0], al1[0]);
            split_f16x2(p10.x, p10.y, ah1[1], al1[1]);
            split_f16x2(p01.x, p01.y, ah1[2], al1[2]);
            split_f16x2(p11.x, p11.y, ah1[3], al1[3]);
        }
        #pragma unroll
        for (int nt = 0; nt < 8; ++nt) {
            MMA_F16(C0[nt], ah0[0], ah0[1], ah0[2], ah0[3], bb[nt].x, bb[nt].y);
            MMA_F16(C1[nt], ah1[0], ah1[1], ah1[2], ah1[3], bb[nt].x, bb[nt].y);
        }
        #pragma unroll
        for (int nt = 0; nt < 8; ++nt) {
            MMA_F16(C0[nt], al0[0], al0[1], al0[2], al0[3], bb[nt].x, bb[nt].y);
            MMA_F16(C1[nt], al1[0], al1[1], al1[2], al1[3], bb[nt].x, bb[nt].y);
        }
    }

    // ---- rope: rows g and g+8 share s -> same cos/sin; both tiles share too ----
    {
        const float* cr = &cs[g * XS_STRIDE];
        const float* sr = &ss[g * XS_STRIDE];
        #pragma unroll
        for (int nt = 0; nt < 4; ++nt) {
            int c = 8*nt + 2*t4;
            float2 cl = *(const float2*)(cr + c);
            float2 ch = *(const float2*)(cr + c + 32);
            float2 sl = *(const float2*)(sr + c);
            float2 sh = *(const float2*)(sr + c + 32);
            #pragma unroll
            for (int e = 0; e < 4; ++e) {
                float cle = (e & 1) ? cl.y : cl.x;
                float che = (e & 1) ? ch.y : ch.x;
                float sle = (e & 1) ? sl.y : sl.x;
                float she = (e & 1) ? sh.y : sh.x;
                float ylo0 = C0[nt][e], yhi0 = C0[nt+4][e];
                C0[nt][e]   = ylo0*cle - yhi0*sle;
                C0[nt+4][e] = yhi0*che + ylo0*she;
                float ylo1 = C1[nt][e], yhi1 = C1[nt+4][e];
                C1[nt][e]   = ylo1*cle - yhi1*sle;
                C1[nt+4][e] = yhi1*che + ylo1*she;
            }
        }
    }

    // ---- park Z in smem (per-thread float4 slots: zs[grp*128 + tid], conflict-free) ----
    __syncthreads();                      // all warps done reading x from xs
    {
        float4* zp = ((float4*)xs) + tid;
        #pragma unroll
        for (int nt = 0; nt < 8; ++nt) {
            float4 v0; v0.x = C0[nt][0]; v0.y = C0[nt][1]; v0.z = C0[nt][2]; v0.w = C0[nt][3];
            float4 v1; v1.x = C1[nt][0]; v1.y = C1[nt][1]; v1.z = C1[nt][2]; v1.w = C1[nt][3];
            zp[nt * 128]       = v0;
            zp[(8 + nt) * 128] = v1;
        }
    }

    // ---- GEMM2: O = Z * Q, A2 re-split per-kt from smem ----
    #pragma unroll
    for (int nt = 0; nt < 8; ++nt)
        #pragma unroll
        for (int e = 0; e < 4; ++e) { C0[nt][e] = 0.0f; C1[nt][e] = 0.0f; }

    {
        const float4* zp = ((const float4*)xs) + tid;
        #pragma unroll
        for (int kt = 0; kt < 4; ++kt) {
            uint2 bb[8];
            #pragma unroll
            for (int nt = 0; nt < 8; ++nt) bb[nt] = g_B2[(kt*8 + nt)*32 + lane];

            float4 z00 = zp[(2*kt) * 128];
            float4 z01 = zp[(2*kt + 1) * 128];
            float4 z10 = zp[(8 + 2*kt) * 128];
            float4 z11 = zp[(8 + 2*kt + 1) * 128];
            uint32_t ah0[4], al0[4], ah1[4], al1[4];
            split_f16x2(z00.x, z00.y, ah0[0], al0[0]);
            split_f16x2(z00.z, z00.w, ah0[1], al0[1]);
            split_f16x2(z01.x, z01.y, ah0[2], al0[2]);
            split_f16x2(z01.z, z01.w, ah0[3], al0[3]);
            split_f16x2(z10.x, z10.y, ah1[0], al1[0]);
            split_f16x2(z10.z, z10.w, ah1[1], al1[1]);
            split_f16x2(z11.x, z11.y, ah1[2], al1[2]);
            split_f16x2(z11.z, z11.w, ah1[3], al1[3]);

            #pragma unroll
            for (int nt = 0; nt < 8; ++nt) {
                MMA_F16(C0[nt], ah0[0], ah0[1], ah0[2], ah0[3], bb[nt].x, bb[nt].y);
                MMA_F16(C1[nt], ah1[0], ah1[1], ah1[2], ah1[3], bb[nt].x, bb[nt].y);
            }
            #pragma unroll
            for (int nt = 0; nt < 8; ++nt) {
                MMA_F16(C0[nt], al0[0], al0[1], al0[2], al0[3], bb[nt].x, bb[nt].y);
                MMA_F16(C1[nt], al1[0], al1[1], al1[2], al1[3], bb[nt].x, bb[nt].y);
            }
        }
    }

    // ---- store: fragments -> smem rows (overwrites zs region), then coalesced flush ----
    __syncthreads();   // all warps done reading Z slots
    #pragma unroll
    for (int tt = 0; tt < 2; ++tt) {
        int tbo = tb + tt * 16;
        float* o0 = &xs[(tbo + g) * XS_STRIDE];
        float* o1 = o0 + 8 * XS_STRIDE;
        #pragma unroll
        for (int nt = 0; nt < 8; ++nt) {
            int c = 8*nt + 2*t4;
            float2 v0, v1;
            if (tt == 0) { v0.x = C0[nt][0]; v0.y = C0[nt][1]; v1.x = C0[nt][2]; v1.y = C0[nt][3]; }
            else         { v0.x = C1[nt][0]; v0.y = C1[nt][1]; v1.x = C1[nt][2]; v1.y = C1[nt][3]; }
            *(float2*)(o0 + c) = v0;
            *(float2*)(o1 + c) = v1;
        }
    }
    __syncthreads();

    const size_t obase = (size_t)tensor * NROWS_Q * DD;
    #pragma unroll
    for (int it = 0; it < 16; ++it) {
        int lin = it * 128 + tid;
        int rl  = lin >> 4;
        int c4  = (lin & 15) << 2;
        int h   = rl >> 3, ds = rl & 7;
        size_t gofs = obase + (((size_t)(b * 16 + h)) * SSS + s0 + ds) * DD + c4;
        *(float4*)(out + gofs) = *(const float4*)&xs[rl * XS_STRIDE + c4];
    }
}

extern "C" void kernel_launch(void* const* d_in, const int* in_sizes, int n_in,
                              void* d_out, int out_size) {
    const float* q    = (const float*)d_in[0];
    const float* k    = (const float*)d_in[1];
    const float* cosp = (const float*)d_in[2];
    const float* sinp = (const float*)d_in[3];
    const float* vs   = (const float*)d_in[4];
    float* out = (float*)d_out;

    build_q_kernel<<<1, 256>>>(vs);
    rnrope_mma_kernel<<<NROWS_T / 128, 128>>>(q, k, cosp, sinp, out);
}

// round 11
// speedup vs baseline: 1.2308x; 1.2308x over previous
#include <cuda_runtime.h>
#include <cuda_fp16.h>
#include <cstdint>

// Shapes fixed by dataset: q/k (4,16,4096,64) f32, cos/sin (4,4096,64) f32, vs (32,64) f32
#define DD 64
#define SSS 4096
#define NROWS_Q (4*16*4096)    // 262144
#define NROWS_T (2*NROWS_Q)    // 524288
#define NREFL 32

// mma-ready packed fp16 B fragments, uint2 = {b0, b1}
// GEMM1: B1[k=j][n=i] = Q[i][j]   (Y = X * Q^T)
// GEMM2: B2[k=i][n=j] = Q[i][j]   (O = Z * Q)
__device__ uint2 g_B1[1024];
__device__ uint2 g_B2[1024];

// ---------------- Kernel A: build Q, barrier-free column-owner scan ----------------
__global__ void build_q_kernel(const float* __restrict__ vs) {
    __shared__ __align__(16) float vsh[NREFL*DD];
    __shared__ float coefs[NREFL];
    __shared__ float Qs[DD*DD];
    const int tid  = threadIdx.x;       // 256
    const int lane = tid & 31;
    const int warp = tid >> 5;

    for (int i = tid; i < NREFL*DD/4; i += 256)
        ((float4*)vsh)[i] = ((const float4*)vs)[i];
    __syncthreads();
    if (tid < NREFL) {
        float s = 0.0f;
        const float4* v4 = (const float4*)&vsh[tid*DD];
        #pragma unroll
        for (int c = 0; c < 16; ++c) {
            float4 v = v4[c];
            s += v.x*v.x + v.y*v.y + v.z*v.z + v.w*v.w;
        }
        coefs[tid] = 2.0f / (s + 1e-8f);
    }
    __syncthreads();

    if (warp < 4) {
        const int col = (warp << 4) | (lane & 15);
        const int seg = lane >> 4;
        float qc[32];
        #pragma unroll
        for (int i = 0; i < 32; ++i) qc[i] = (seg*32 + i == col) ? 1.0f : 0.0f;

        for (int r = 0; r < NREFL; ++r) {
            const float4* v4 = (const float4*)&vsh[r*DD + seg*32];
            float4 vv[8];
            #pragma unroll
            for (int i = 0; i < 8; ++i) vv[i] = v4[i];
            float w0 = 0.f, w1 = 0.f, w2 = 0.f, w3 = 0.f;
            #pragma unroll
            for (int i = 0; i < 8; ++i) {
                w0 += vv[i].x * qc[4*i];
                w1 += vv[i].y * qc[4*i+1];
                w2 += vv[i].z * qc[4*i+2];
                w3 += vv[i].w * qc[4*i+3];
            }
            float w = (w0 + w1) + (w2 + w3);
            w += __shfl_xor_sync(0xffffffffu, w, 16);
            float cw = coefs[r] * w;
            #pragma unroll
            for (int i = 0; i < 8; ++i) {
                qc[4*i]   -= vv[i].x * cw;
                qc[4*i+1] -= vv[i].y * cw;
                qc[4*i+2] -= vv[i].z * cw;
                qc[4*i+3] -= vv[i].w * cw;
            }
        }
        #pragma unroll
        for (int i = 0; i < 32; ++i) Qs[(seg*32 + i)*DD + col] = qc[i];
    }
    __syncthreads();

    for (int slot = tid; slot < 1024; slot += 256) {
        int l = slot & 31, frag = slot >> 5;
        int kt = frag >> 3, nt = frag & 7;
        int g = l >> 2, t4 = l & 3;
        int n  = 8*nt + g;
        int k0 = 16*kt + 2*t4;
        {
            __half2 h0 = __floats2half2_rn(Qs[n*DD + k0],     Qs[n*DD + k0 + 1]);
            __half2 h1 = __floats2half2_rn(Qs[n*DD + k0 + 8], Qs[n*DD + k0 + 9]);
            g_B1[slot] = make_uint2(*(uint32_t*)&h0, *(uint32_t*)&h1);
        }
        {
            __half2 h0 = __floats2half2_rn(Qs[k0*DD + n],     Qs[(k0+1)*DD + n]);
            __half2 h1 = __floats2half2_rn(Qs[(k0+8)*DD + n], Qs[(k0+9)*DD + n]);
            g_B2[slot] = make_uint2(*(uint32_t*)&h0, *(uint32_t*)&h1);
        }
    }
}

// ---------------- helpers ----------------
__device__ __forceinline__ uint32_t pk_f16x2(float a, float b) {
    __half2 h = __floats2half2_rn(a, b);
    return *(uint32_t*)&h;
}

#define MMA_F16(c, a0, a1, a2, a3, b0, b1)                                         \
    asm volatile("mma.sync.aligned.m16n8k16.row.col.f32.f16.f16.f32 "              \
                 "{%0,%1,%2,%3}, {%4,%5,%6,%7}, {%8,%9}, {%0,%1,%2,%3};"           \
                 : "+f"(c[0]), "+f"(c[1]), "+f"(c[2]), "+f"(c[3])                   \
                 : "r"(a0), "r"(a1), "r"(a2), "r"(a3), "r"(b0), "r"(b1))

// ---------------- Kernel B ----------------
// Block = 128 threads (4 warps), ONE (tensor, b, s-chunk of 8) x 16 heads = 128 rows.
// Each warp: TWO 16-row M-tiles. Single-term fp16 MMA (A and B both rounded to fp16;
// fp32 accumulate). A1 built per-kt (transient regs); A2 built upfront from C.
#define XS_STRIDE 68
__global__ void __launch_bounds__(128, 4) rnrope_mma_kernel(
    const float* __restrict__ qin, const float* __restrict__ kin,
    const float* __restrict__ cosp, const float* __restrict__ sinp,
    float* __restrict__ out)
{
    __shared__ __align__(16) float xs[128 * XS_STRIDE];   // x tile; reused for out tile
    __shared__ __align__(16) float cs[8 * XS_STRIDE];
    __shared__ __align__(16) float ss[8 * XS_STRIDE];

    const int tid  = threadIdx.x;
    const int warp = tid >> 5;
    const int lane = tid & 31;
    const int g    = lane >> 2;
    const int t4   = lane & 3;

    const int bid    = blockIdx.x;          // 4096 blocks
    const int tensor = bid >> 11;           // 0 = q, 1 = k
    const int b      = (bid >> 9) & 3;
    const int s0     = (bid & 511) << 3;
    const float* src = tensor ? kin : qin;

    // ---- stage cos/sin (8 rows x 64) ----
    {
        int r  = tid >> 4;
        int c4 = (tid & 15) << 2;
        size_t gofs = ((size_t)(b * SSS + s0 + r)) * DD + c4;
        *(float4*)&cs[r * XS_STRIDE + c4] = *(const float4*)(cosp + gofs);
        *(float4*)&ss[r * XS_STRIDE + c4] = *(const float4*)(sinp + gofs);
    }
    // ---- stage x (128 rows x 64), coalesced per 8-row head chunk ----
    #pragma unroll
    for (int it = 0; it < 16; ++it) {
        int lin = it * 128 + tid;
        int rl  = lin >> 4;
        int c4  = (lin & 15) << 2;
        int h   = rl >> 3, ds = rl & 7;
        size_t gofs = (((size_t)(b * 16 + h)) * SSS + s0 + ds) * DD + c4;
        *(float4*)&xs[rl * XS_STRIDE + c4] = *(const float4*)(src + gofs);
    }
    __syncthreads();

    const int tb = warp * 32;
    const float* x0a = &xs[(tb + g) * XS_STRIDE];        // tile0 row g
    const float* x0b = x0a + 8 * XS_STRIDE;              // tile0 row g+8
    const float* x1a = &xs[(tb + 16 + g) * XS_STRIDE];   // tile1
    const float* x1b = x1a + 8 * XS_STRIDE;

    // ---- GEMM1: Y = X * Q^T (single-term fp16), A built per-kt ----
    float C0[8][4], C1[8][4];
    #pragma unroll
    for (int nt = 0; nt < 8; ++nt)
        #pragma unroll
        for (int e = 0; e < 4; ++e) { C0[nt][e] = 0.0f; C1[nt][e] = 0.0f; }

    #pragma unroll
    for (int kt = 0; kt < 4; ++kt) {
        uint2 bb[8];
        #pragma unroll
        for (int nt = 0; nt < 8; ++nt) bb[nt] = g_B1[(kt*8 + nt)*32 + lane];

        const int c0 = kt * 16 + 2 * t4;
        uint32_t a0[4], a1[4];
        {
            float2 p00 = *(const float2*)(x0a + c0);
            float2 p01 = *(const float2*)(x0a + c0 + 8);
            float2 p10 = *(const float2*)(x0b + c0);
            float2 p11 = *(const float2*)(x0b + c0 + 8);
            a0[0] = pk_f16x2(p00.x, p00.y);
            a0[1] = pk_f16x2(p10.x, p10.y);
            a0[2] = pk_f16x2(p01.x, p01.y);
            a0[3] = pk_f16x2(p11.x, p11.y);
        }
        {
            float2 p00 = *(const float2*)(x1a + c0);
            float2 p01 = *(const float2*)(x1a + c0 + 8);
            float2 p10 = *(const float2*)(x1b + c0);
            float2 p11 = *(const float2*)(x1b + c0 + 8);
            a1[0] = pk_f16x2(p00.x, p00.y);
            a1[1] = pk_f16x2(p10.x, p10.y);
            a1[2] = pk_f16x2(p01.x, p01.y);
            a1[3] = pk_f16x2(p11.x, p11.y);
        }
        #pragma unroll
        for (int nt = 0; nt < 8; ++nt) {
            MMA_F16(C0[nt], a0[0], a0[1], a0[2], a0[3], bb[nt].x, bb[nt].y);
            MMA_F16(C1[nt], a1[0], a1[1], a1[2], a1[3], bb[nt].x, bb[nt].y);
        }
    }

    // ---- rope: rows g and g+8 share s -> same cos/sin; both tiles share too ----
    {
        const float* cr = &cs[g * XS_STRIDE];
        const float* sr = &ss[g * XS_STRIDE];
        #pragma unroll
        for (int nt = 0; nt < 4; ++nt) {
            int c = 8*nt + 2*t4;
            float2 cl = *(const float2*)(cr + c);
            float2 ch = *(const float2*)(cr + c + 32);
            float2 sl = *(const float2*)(sr + c);
            float2 sh = *(const float2*)(sr + c + 32);
            #pragma unroll
            for (int e = 0; e < 4; ++e) {
                float cle = (e & 1) ? cl.y : cl.x;
                float che = (e & 1) ? ch.y : ch.x;
                float sle = (e & 1) ? sl.y : sl.x;
                float she = (e & 1) ? sh.y : sh.x;
                float ylo0 = C0[nt][e], yhi0 = C0[nt+4][e];
                C0[nt][e]   = ylo0*cle - yhi0*sle;
                C0[nt+4][e] = yhi0*che + ylo0*she;
                float ylo1 = C1[nt][e], yhi1 = C1[nt+4][e];
                C1[nt][e]   = ylo1*cle - yhi1*sle;
                C1[nt+4][e] = yhi1*che + ylo1*she;
            }
        }
    }

    // ---- Z -> A2 fragments (fp16, single-term) ----
    uint32_t A20[4][4], A21[4][4];
    #pragma unroll
    for (int kt = 0; kt < 4; ++kt) {
        A20[kt][0] = pk_f16x2(C0[2*kt][0],   C0[2*kt][1]);
        A20[kt][1] = pk_f16x2(C0[2*kt][2],   C0[2*kt][3]);
        A20[kt][2] = pk_f16x2(C0[2*kt+1][0], C0[2*kt+1][1]);
        A20[kt][3] = pk_f16x2(C0[2*kt+1][2], C0[2*kt+1][3]);
        A21[kt][0] = pk_f16x2(C1[2*kt][0],   C1[2*kt][1]);
        A21[kt][1] = pk_f16x2(C1[2*kt][2],   C1[2*kt][3]);
        A21[kt][2] = pk_f16x2(C1[2*kt+1][0], C1[2*kt+1][1]);
        A21[kt][3] = pk_f16x2(C1[2*kt+1][2], C1[2*kt+1][3]);
    }

    // ---- GEMM2: O = Z * Q ----
    #pragma unroll
    for (int nt = 0; nt < 8; ++nt)
        #pragma unroll
        for (int e = 0; e < 4; ++e) { C0[nt][e] = 0.0f; C1[nt][e] = 0.0f; }

    #pragma unroll
    for (int kt = 0; kt < 4; ++kt) {
        uint2 bb[8];
        #pragma unroll
        for (int nt = 0; nt < 8; ++nt) bb[nt] = g_B2[(kt*8 + nt)*32 + lane];
        #pragma unroll
        for (int nt = 0; nt < 8; ++nt) {
            MMA_F16(C0[nt], A20[kt][0], A20[kt][1], A20[kt][2], A20[kt][3], bb[nt].x, bb[nt].y);
            MMA_F16(C1[nt], A21[kt][0], A21[kt][1], A21[kt][2], A21[kt][3], bb[nt].x, bb[nt].y);
        }
    }

    // ---- store: fragments -> smem (reuse xs), then coalesced flush ----
    __syncthreads();   // all warps done reading xs
    #pragma unroll
    for (int tt = 0; tt < 2; ++tt) {
        int tbo = tb + tt * 16;
        float* o0 = &xs[(tbo + g) * XS_STRIDE];
        float* o1 = o0 + 8 * XS_STRIDE;
        #pragma unroll
        for (int nt = 0; nt < 8; ++nt) {
            int c = 8*nt + 2*t4;
            float2 v0, v1;
            if (tt == 0) { v0.x = C0[nt][0]; v0.y = C0[nt][1]; v1.x = C0[nt][2]; v1.y = C0[nt][3]; }
            else         { v0.x = C1[nt][0]; v0.y = C1[nt][1]; v1.x = C1[nt][2]; v1.y = C1[nt][3]; }
            *(float2*)(o0 + c) = v0;
            *(float2*)(o1 + c) = v1;
        }
    }
    __syncthreads();

    const size_t obase = (size_t)tensor * NROWS_Q * DD;
    #pragma unroll
    for (int it = 0; it < 16; ++it) {
        int lin = it * 128 + tid;
        int rl  = lin >> 4;
        int c4  = (lin & 15) << 2;
        int h   = rl >> 3, ds = rl & 7;
        size_t gofs = obase + (((size_t)(b * 16 + h)) * SSS + s0 + ds) * DD + c4;
        *(float4*)(out + gofs) = *(const float4*)&xs[rl * XS_STRIDE + c4];
    }
}

extern "C" void kernel_launch(void* const* d_in, const int* in_sizes, int n_in,
                              void* d_out, int out_size) {
    const float* q    = (const float*)d_in[0];
    const float* k    = (const float*)d_in[1];
    const float* cosp = (const float*)d_in[2];
    const float* sinp = (const float*)d_in[3];
    const float* vs   = (const float*)d_in[4];
    float* out = (float*)d_out;

    build_q_kernel<<<1, 256>>>(vs);
    rnrope_mma_kernel<<<NROWS_T / 128, 128>>>(q, k, cosp, sinp, out);
}